// round 5
// baseline (speedup 1.0000x reference)
#include <cuda_runtime.h>

// Problem constants
#define T_TOKENS 32768      // B*S
#define TM 32               // tokens per CTA
#define NTHREADS 512
#define DK 8                // d-chunk depth
#define BP 1024             // Bs row pitch (floats) — natural, cp.async'd, no transpose
#define AP2 68              // As row pitch (floats): 64 duplicated-pair floats + pad (16B-aligned rows)

// Output layout (float element offsets): quantized | indices | quant | avg_probs | x
#define OFF_Q     0
#define OFF_IDX   33554432
#define OFF_QUANT 33685504
#define OFF_AVG   67239936
#define OFF_X     100794368

// smem layout (float offsets)
#define S_BS0  0
#define S_BS1  (DK*BP)                 // 8192
#define S_AS0  (2*DK*BP)               // 16384
#define S_AS1  (S_AS0 + DK*AP2)        // 16928
#define S_PACC (S_AS1 + DK*AP2)        // 17472 (16B aligned)
#define S_REDM (S_PACC + TM*1024)      // 50240
#define S_REDI (S_REDM + 128)
#define S_REDZ (S_REDI + 128)
#define S_FIDX (S_REDZ + 128)
#define SM_FLOATS (S_FIDX + 32)        // 50656 floats = 202,624 B

// 4 MB transposed codebook scratch: cbT[l][d][k]
__device__ float cbT_g[4 * 256 * 1024];

static __device__ __forceinline__ unsigned long long pack2b(float lo, float hi) {
    unsigned long long r;
    asm("mov.b64 %0, {%1, %2};" : "=l"(r) : "f"(lo), "f"(hi));
    return r;
}
// d = a * b + d on packed f32x2 (SASS FFMA2 — 2x scalar FFMA throughput)
static __device__ __forceinline__ void ffma2(unsigned long long& d,
                                             unsigned long long a,
                                             unsigned long long b) {
    asm("fma.rn.f32x2 %0, %1, %2, %0;" : "+l"(d) : "l"(a), "l"(b));
}
static __device__ __forceinline__ float lo32(unsigned long long v) {
    return __uint_as_float((unsigned)v);
}
static __device__ __forceinline__ float hi32(unsigned long long v) {
    return __uint_as_float((unsigned)(v >> 32));
}
static __device__ __forceinline__ void cp16(float* smem_dst, const float* gsrc) {
    unsigned s = (unsigned)__cvta_generic_to_shared(smem_dst);
    asm volatile("cp.async.cg.shared.global [%0], [%1], 16;" :: "r"(s), "l"(gsrc));
}
#define CP_COMMIT() asm volatile("cp.async.commit_group;")
#define CP_WAIT0()  asm volatile("cp.async.wait_group 0;")

// ---------- pre-pass: codebook transpose cb[l][k][d] -> cbT[l][d][k] ----------
__global__ void transpose_cb(const float* __restrict__ cb)
{
    __shared__ float tile[32][33];
    const int l  = blockIdx.z;
    const int db = blockIdx.x * 32;     // d block
    const int kb = blockIdx.y * 32;     // k block
    const float* src = cb + l * 262144;
    float* dst = cbT_g + l * 262144;
    const int tx = threadIdx.x, ty0 = threadIdx.y;   // block (32, 8)
    #pragma unroll
    for (int i = 0; i < 4; ++i) {
        int k = kb + ty0 + i * 8;
        tile[ty0 + i * 8][tx] = src[k * 256 + db + tx];
    }
    __syncthreads();
    #pragma unroll
    for (int i = 0; i < 4; ++i) {
        int d = db + ty0 + i * 8;
        dst[d * 1024 + kb + tx] = tile[tx][ty0 + i * 8];
    }
}

// ---------- main kernel ----------
__global__ __launch_bounds__(NTHREADS, 1)
void ahq_kernel(const float* __restrict__ x,
                const float* __restrict__ cb,
                const float* __restrict__ temp,
                float* __restrict__ out)
{
    extern __shared__ float sm[];
    float* Pacc = sm + S_PACC;
    float* redM = sm + S_REDM;
    int*   redI = (int*)(sm + S_REDI);
    float* redZ = sm + S_REDZ;
    int*   fidx = (int*)(sm + S_FIDX);

    const int t      = threadIdx.x;
    const int tx     = t & 127;          // code axis: 128 threads x 8 codes
    const int ty     = t >> 7;           // token-group axis: 4 groups x 8 tokens
    const int warp_g = (t >> 5) & 3;     // warp index within token-group
    const int lane0  = ((t & 31) == 0);
    const int token0 = blockIdx.x * TM;
    const float inv_tau = 1.0f / fmaxf(temp[0], 0.04f);

    // zero avg-probs accumulator
    {
        float4 z = make_float4(0.f, 0.f, 0.f, 0.f);
        float4* P4 = (float4*)Pacc;
        #pragma unroll
        for (int i = 0; i < (TM * 1024) / (4 * NTHREADS); ++i)
            P4[t + i * NTHREADS] = z;
    }

    unsigned long long acc2[32];   // 8 tokens x 8 codes as packed code-pairs
    float4 rA;                     // x staging (threads 0..63)

    for (int l = 0; l < 4; ++l) {
        #pragma unroll
        for (int i = 0; i < 32; ++i) acc2[i] = 0ULL;

        // async copy of d-major B chunk (32 KB contiguous in cbT)
        auto cpB = [&](float* Bb, int d0) {
            const float* src = cbT_g + (l << 18) + (d0 << 10) + (t << 2);
            float* dst = Bb + (t << 2);
            #pragma unroll
            for (int p = 0; p < 4; ++p)
                cp16(dst + (p << 11), src + (p << 11));
        };
        auto ldgA = [&](int d0) {
            if (t < 64) {
                int tok = t >> 1;
                int dj  = (t & 1) << 2;
                int xi = ((token0 + tok) << 10) + (l << 8) + d0 + dj;
                rA = *(const float4*)(x + xi);
                *(float4*)(out + OFF_X + xi) = rA;   // fused x copy (each elem once)
            }
        };
        auto stsA = [&](float* Ab) {
            if (t < 64) {
                int tok = t >> 1;
                int dj  = (t & 1) << 2;
                int c2  = tok << 1;                   // duplicated-pair column
                float a0 = rA.x * inv_tau, a1 = rA.y * inv_tau;
                float a2 = rA.z * inv_tau, a3 = rA.w * inv_tau;
                Ab[(dj + 0) * AP2 + c2] = a0;  Ab[(dj + 0) * AP2 + c2 + 1] = a0;
                Ab[(dj + 1) * AP2 + c2] = a1;  Ab[(dj + 1) * AP2 + c2 + 1] = a1;
                Ab[(dj + 2) * AP2 + c2] = a2;  Ab[(dj + 2) * AP2 + c2 + 1] = a2;
                Ab[(dj + 3) * AP2 + c2] = a3;  Ab[(dj + 3) * AP2 + c2 + 1] = a3;
            }
        };
        auto compute = [&](const float* Bb, const float* Ab) {
            #pragma unroll
            for (int d = 0; d < DK; ++d) {
                const float* Bd = Bb + d * BP + (tx << 2);
                const float* Ad = Ab + d * AP2 + (ty << 4);   // 8 tokens * 2 dup floats
                ulonglong2 b0 = *(const ulonglong2*)Bd;         // codes tx*4 .. +3
                ulonglong2 b1 = *(const ulonglong2*)(Bd + 512); // codes 512+tx*4 .. +3
                #pragma unroll
                for (int pp = 0; pp < 4; ++pp) {
                    // broadcast LDS.128: two tokens' duplicated pairs, no MOVs
                    ulonglong2 av = *(const ulonglong2*)(Ad + (pp << 2));
                    const int t0 = pp << 1;
                    ffma2(acc2[t0 * 4 + 0], av.x, b0.x);
                    ffma2(acc2[t0 * 4 + 1], av.x, b0.y);
                    ffma2(acc2[t0 * 4 + 2], av.x, b1.x);
                    ffma2(acc2[t0 * 4 + 3], av.x, b1.y);
                    ffma2(acc2[(t0 + 1) * 4 + 0], av.y, b0.x);
                    ffma2(acc2[(t0 + 1) * 4 + 1], av.y, b0.y);
                    ffma2(acc2[(t0 + 1) * 4 + 2], av.y, b1.x);
                    ffma2(acc2[(t0 + 1) * 4 + 3], av.y, b1.y);
                }
            }
        };

        // double-buffered chunk pipeline: ONE barrier per chunk
        ldgA(0);
        cpB(sm + S_BS0, 0);
        CP_COMMIT();
        stsA(sm + S_AS0);
        CP_WAIT0();
        __syncthreads();
        #pragma unroll 1
        for (int c = 0; c < 32; ++c) {
            float* Bcur = sm + ((c & 1) ? S_BS1 : S_BS0);
            float* Acur = sm + ((c & 1) ? S_AS1 : S_AS0);
            float* Bnxt = sm + ((c & 1) ? S_BS0 : S_BS1);
            float* Anxt = sm + ((c & 1) ? S_AS0 : S_AS1);
            if (c + 1 < 32) {
                ldgA((c + 1) * DK);
                cpB(Bnxt, (c + 1) * DK);
                CP_COMMIT();
            }
            compute(Bcur, Acur);
            if (c + 1 < 32) {
                stsA(Anxt);
                CP_WAIT0();
            }
            __syncthreads();
        }

        // ================= epilogue for layer l =================
        // 1) argmax (first-occurrence tie-break on smaller code index)
        float M[8]; int MI[8]; float Zq[8];
        #pragma unroll
        for (int tt = 0; tt < 8; ++tt) {
            float m = -3.4e38f; int mi = 0;
            #pragma unroll
            for (int q = 0; q < 4; ++q) {
                unsigned long long v = acc2[tt * 4 + q];
                int code = ((q >> 1) << 9) + (tx << 2) + ((q & 1) << 1);
                float flo = lo32(v), fhi = hi32(v);
                if (flo > m) { m = flo; mi = code; }
                if (fhi > m) { m = fhi; mi = code + 1; }
            }
            #pragma unroll
            for (int off = 16; off > 0; off >>= 1) {
                float om = __shfl_down_sync(0xffffffffu, m, off);
                int   oi = __shfl_down_sync(0xffffffffu, mi, off);
                if (om > m || (om == m && oi < mi)) { m = om; mi = oi; }
            }
            M[tt] = m; MI[tt] = mi;
        }
        if (lane0) {
            #pragma unroll
            for (int tt = 0; tt < 8; ++tt) {
                int r = (((ty << 3) + tt) << 2) + warp_g;
                redM[r] = M[tt]; redI[r] = MI[tt];
            }
        }
        __syncthreads();
        #pragma unroll
        for (int tt = 0; tt < 8; ++tt) {
            int r = ((ty << 3) + tt) << 2;
            float m = redM[r]; int mi = redI[r];
            #pragma unroll
            for (int g = 1; g < 4; ++g) {
                float om = redM[r + g]; int oi = redI[r + g];
                if (om > m || (om == m && oi < mi)) { m = om; mi = oi; }
            }
            M[tt] = m; MI[tt] = mi;
        }
        // 2) exp + denominator (overwrite acc2 with exp values)
        #pragma unroll
        for (int tt = 0; tt < 8; ++tt) {
            float s = 0.0f;
            #pragma unroll
            for (int q = 0; q < 4; ++q) {
                unsigned long long v = acc2[tt * 4 + q];
                float elo = __expf(lo32(v) - M[tt]);
                float ehi = __expf(hi32(v) - M[tt]);
                s += elo + ehi;
                acc2[tt * 4 + q] = pack2b(elo, ehi);
            }
            #pragma unroll
            for (int off = 16; off > 0; off >>= 1)
                s += __shfl_down_sync(0xffffffffu, s, off);
            if (lane0) redZ[(((ty << 3) + tt) << 2) + warp_g] = s;
        }
        __syncthreads();
        #pragma unroll
        for (int tt = 0; tt < 8; ++tt) {
            int r = ((ty << 3) + tt) << 2;
            Zq[tt] = 0.25f / (redZ[r] + redZ[r + 1] + redZ[r + 2] + redZ[r + 3]);
        }
        // 3) accumulate avg probs in smem; write indices; publish argmax for gather
        #pragma unroll
        for (int tt = 0; tt < 8; ++tt) {
            int tloc = (ty << 3) + tt;
            unsigned long long iz = pack2b(Zq[tt], Zq[tt]);
            unsigned long long* P2 = (unsigned long long*)(Pacc + (tloc << 10));
            ulonglong2 pv0 = *(ulonglong2*)(P2 + (tx << 1));
            ffma2(pv0.x, acc2[tt * 4 + 0], iz);
            ffma2(pv0.y, acc2[tt * 4 + 1], iz);
            *(ulonglong2*)(P2 + (tx << 1)) = pv0;
            ulonglong2 pv1 = *(ulonglong2*)(P2 + 256 + (tx << 1));
            ffma2(pv1.x, acc2[tt * 4 + 2], iz);
            ffma2(pv1.y, acc2[tt * 4 + 3], iz);
            *(ulonglong2*)(P2 + 256 + (tx << 1)) = pv1;
            if (tx == 0) {
                out[OFF_IDX + (token0 + tloc) * 4 + l] = (float)MI[tt];
                fidx[tloc] = MI[tt];
            }
        }
        __syncthreads();
        // 4) hard_q gather: 16 threads per token
        {
            int tokg   = t >> 4;
            int lane16 = t & 15;
            int mi = fidx[tokg];
            const float4* crow = (const float4*)(cb + (((l << 10) + mi) << 8));
            int qbase = (token0 + tokg) * 256 + (l << 6) + lane16;   // float4 units
            #pragma unroll
            for (int p = 0; p < 4; ++p) {
                float4 q = crow[(p << 4) + lane16];
                ((float4*)out)[(OFF_Q     >> 2) + qbase + (p << 4)] = q;   // quantized
                ((float4*)out)[(OFF_QUANT >> 2) + qbase + (p << 4)] = q;   // quant
            }
        }
        // chunk-loop barriers of the next layer order red/fidx reuse
    }

    // final avg_code_probs write (each thread writes cells it alone accumulated)
    #pragma unroll
    for (int tt = 0; tt < 8; ++tt) {
        int tloc = (ty << 3) + tt;
        const float4* Pp = (const float4*)(Pacc + (tloc << 10));
        int gbase = (token0 + tloc) * 256;   // float4 units (row = 1024 floats)
        ((float4*)out)[(OFF_AVG >> 2) + gbase + tx]       = Pp[tx];
        ((float4*)out)[(OFF_AVG >> 2) + gbase + 128 + tx] = Pp[128 + tx];
    }
}

extern "C" void kernel_launch(void* const* d_in, const int* in_sizes, int n_in,
                              void* d_out, int out_size)
{
    const float* x    = (const float*)d_in[0];
    const float* cb   = (const float*)d_in[1];
    const float* temp = (const float*)d_in[2];
    float* out = (float*)d_out;
    (void)in_sizes; (void)n_in; (void)out_size;

    // pre-pass: transpose codebook into cbT_g (d-major)
    transpose_cb<<<dim3(8, 32, 4), dim3(32, 8)>>>(cb);

    size_t smem = SM_FLOATS * sizeof(float);   // ~202.6 KB (< 227 KB sm_103a cap)
    cudaFuncSetAttribute(ahq_kernel, cudaFuncAttributeMaxDynamicSharedMemorySize, (int)smem);
    ahq_kernel<<<T_TOKENS / TM, NTHREADS, smem>>>(x, cb, temp, out);
}

// round 6
// speedup vs baseline: 1.1958x; 1.1958x over previous
#include <cuda_runtime.h>

// Problem constants
#define T_TOKENS 32768      // B*S
#define TM 32               // tokens per CTA
#define NTHREADS 512
#define DK 16               // d-chunk depth (16 chunks per layer)
#define BP 1024             // Bs row pitch (floats) — natural, cp.async'd, no transpose
#define AP 36               // As row pitch (floats)

// Output layout (float element offsets): quantized | indices | quant | avg_probs | x
#define OFF_Q     0
#define OFF_IDX   33554432
#define OFF_QUANT 33685504
#define OFF_AVG   67239936
#define OFF_X     100794368

// smem layout (float offsets)
#define S_BS0  0
#define S_BS1  (DK*BP)                 // 16384
#define S_AS0  (2*DK*BP)               // 32768
#define S_AS1  (S_AS0 + DK*AP)         // 33344
#define S_REDM (S_AS1 + DK*AP)         // 33920
#define S_REDI (S_REDM + 64)
#define S_REDZ (S_REDI + 64)
#define SM_FLOATS (S_REDZ + 64)        // 34112 floats = 136,448 B

// 4 MB transposed codebook scratch: cbT[l][d][k]
__device__ float cbT_g[4 * 256 * 1024];

static __device__ __forceinline__ unsigned long long pack2(float x) {
    unsigned long long r;
    asm("mov.b64 %0, {%1, %1};" : "=l"(r) : "f"(x));
    return r;
}
static __device__ __forceinline__ unsigned long long pack2b(float lo, float hi) {
    unsigned long long r;
    asm("mov.b64 %0, {%1, %2};" : "=l"(r) : "f"(lo), "f"(hi));
    return r;
}
// d = a * b + d on packed f32x2 (SASS FFMA2 — 2x scalar FFMA throughput)
static __device__ __forceinline__ void ffma2(unsigned long long& d,
                                             unsigned long long a,
                                             unsigned long long b) {
    asm("fma.rn.f32x2 %0, %1, %2, %0;" : "+l"(d) : "l"(a), "l"(b));
}
static __device__ __forceinline__ float lo32(unsigned long long v) {
    return __uint_as_float((unsigned)v);
}
static __device__ __forceinline__ float hi32(unsigned long long v) {
    return __uint_as_float((unsigned)(v >> 32));
}
static __device__ __forceinline__ void cp16(float* smem_dst, const float* gsrc) {
    unsigned s = (unsigned)__cvta_generic_to_shared(smem_dst);
    asm volatile("cp.async.cg.shared.global [%0], [%1], 16;" :: "r"(s), "l"(gsrc));
}
#define CP_COMMIT() asm volatile("cp.async.commit_group;")
#define CP_WAIT0()  asm volatile("cp.async.wait_group 0;")

// ---------- pre-pass: codebook transpose cb[l][k][d] -> cbT[l][d][k] ----------
__global__ void transpose_cb(const float* __restrict__ cb)
{
    __shared__ float tile[32][33];
    const int l  = blockIdx.z;
    const int db = blockIdx.x * 32;     // d block
    const int kb = blockIdx.y * 32;     // k block
    const float* src = cb + l * 262144;
    float* dst = cbT_g + l * 262144;
    const int tx = threadIdx.x, ty0 = threadIdx.y;   // block (32, 8)
    #pragma unroll
    for (int i = 0; i < 4; ++i) {
        int k = kb + ty0 + i * 8;
        tile[ty0 + i * 8][tx] = src[k * 256 + db + tx];
    }
    __syncthreads();
    #pragma unroll
    for (int i = 0; i < 4; ++i) {
        int d = db + ty0 + i * 8;
        dst[d * 1024 + kb + tx] = tile[tx][ty0 + i * 8];
    }
}

// ---------- main kernel ----------
__global__ __launch_bounds__(NTHREADS, 1)
void ahq_kernel(const float* __restrict__ x,
                const float* __restrict__ cb,
                const float* __restrict__ temp,
                float* __restrict__ out)
{
    extern __shared__ float sm[];
    float* redM = sm + S_REDM;
    int*   redI = (int*)(sm + S_REDI);
    float* redZ = sm + S_REDZ;

    const int t      = threadIdx.x;
    const int tx     = t & 63;           // code-group axis (64)
    const int ty     = t >> 6;           // token-group axis (8)
    const int half   = tx >> 5;          // warp-half within the 64 threads of a token row
    const int token0 = blockIdx.x * TM;
    const float inv_tau = 1.0f / fmaxf(temp[0], 0.04f);

    unsigned long long acc2[32];   // 4 tokens x 16 codes as packed code-pairs
    float4 rA;                     // x staging (threads 0..127)

    for (int l = 0; l < 4; ++l) {
        #pragma unroll
        for (int i = 0; i < 32; ++i) acc2[i] = 0ULL;

        // async copy of d-major B chunk (64 KB contiguous in cbT)
        auto cpB = [&](float* Bb, int d0) {
            const float* src = cbT_g + (l << 18) + (d0 << 10) + (t << 2);
            float* dst = Bb + (t << 2);
            #pragma unroll
            for (int p = 0; p < 8; ++p)
                cp16(dst + (p << 11), src + (p << 11));
        };
        auto ldgA = [&](int d0) {
            if (t < 128) {
                int tok = t >> 2;
                int dj  = (t & 3) << 2;
                int xi = ((token0 + tok) << 10) + (l << 8) + d0 + dj;
                rA = *(const float4*)(x + xi);
                *(float4*)(out + OFF_X + xi) = rA;   // fused x copy (each elem once)
            }
        };
        auto stsA = [&](float* Ab) {
            if (t < 128) {
                int tok = t >> 2;
                int dj  = (t & 3) << 2;
                Ab[(dj + 0) * AP + tok] = rA.x * inv_tau;
                Ab[(dj + 1) * AP + tok] = rA.y * inv_tau;
                Ab[(dj + 2) * AP + tok] = rA.z * inv_tau;
                Ab[(dj + 3) * AP + tok] = rA.w * inv_tau;
            }
        };
        auto compute = [&](const float* Bb, const float* Ab) {
            #pragma unroll
            for (int d = 0; d < DK; ++d) {
                float4 a4 = *(const float4*)(Ab + d * AP + (ty << 2));
                unsigned long long pa0 = pack2(a4.x);
                unsigned long long pa1 = pack2(a4.y);
                unsigned long long pa2 = pack2(a4.z);
                unsigned long long pa3 = pack2(a4.w);
                #pragma unroll
                for (int j = 0; j < 4; ++j) {
                    ulonglong2 bv = *(const ulonglong2*)(Bb + d * BP + (j << 8) + (tx << 2));
                    ffma2(acc2[0 * 8 + j * 2 + 0], pa0, bv.x);
                    ffma2(acc2[0 * 8 + j * 2 + 1], pa0, bv.y);
                    ffma2(acc2[1 * 8 + j * 2 + 0], pa1, bv.x);
                    ffma2(acc2[1 * 8 + j * 2 + 1], pa1, bv.y);
                    ffma2(acc2[2 * 8 + j * 2 + 0], pa2, bv.x);
                    ffma2(acc2[2 * 8 + j * 2 + 1], pa2, bv.y);
                    ffma2(acc2[3 * 8 + j * 2 + 0], pa3, bv.x);
                    ffma2(acc2[3 * 8 + j * 2 + 1], pa3, bv.y);
                }
            }
        };

        // double-buffered chunk pipeline: ONE barrier per chunk (16 chunks)
        ldgA(0);
        cpB(sm + S_BS0, 0);
        CP_COMMIT();
        stsA(sm + S_AS0);
        CP_WAIT0();
        __syncthreads();
        #pragma unroll 1
        for (int c = 0; c < 16; ++c) {
            float* Bcur = sm + ((c & 1) ? S_BS1 : S_BS0);
            float* Acur = sm + ((c & 1) ? S_AS1 : S_AS0);
            float* Bnxt = sm + ((c & 1) ? S_BS0 : S_BS1);
            float* Anxt = sm + ((c & 1) ? S_AS0 : S_AS1);
            if (c + 1 < 16) {
                ldgA((c + 1) * DK);
                cpB(Bnxt, (c + 1) * DK);
                CP_COMMIT();
            }
            compute(Bcur, Acur);
            if (c + 1 < 16) {
                stsA(Anxt);
                CP_WAIT0();
            }
            __syncthreads();
        }

        // ================= epilogue for layer l =================
        // 1) argmax (first-occurrence tie-break on smaller code index)
        float M[4]; int MI[4];
        #pragma unroll
        for (int tt = 0; tt < 4; ++tt) {
            float m = -3.4e38f; int mi = 0;
            #pragma unroll
            for (int h = 0; h < 8; ++h) {
                unsigned long long v = acc2[tt * 8 + h];
                float flo = lo32(v), fhi = hi32(v);
                int code = ((h >> 1) << 8) + (tx << 2) + ((h & 1) << 1);
                if (flo > m) { m = flo; mi = code; }
                if (fhi > m) { m = fhi; mi = code + 1; }
            }
            #pragma unroll
            for (int off = 16; off > 0; off >>= 1) {
                float om = __shfl_down_sync(0xffffffffu, m, off);
                int   oi = __shfl_down_sync(0xffffffffu, mi, off);
                if (om > m || (om == m && oi < mi)) { m = om; mi = oi; }
            }
            M[tt] = m; MI[tt] = mi;
        }
        if ((tx & 31) == 0) {
            #pragma unroll
            for (int tt = 0; tt < 4; ++tt) {
                redM[((((ty << 2) + tt) << 1)) + half] = M[tt];
                redI[((((ty << 2) + tt) << 1)) + half] = MI[tt];
            }
        }
        __syncthreads();
        #pragma unroll
        for (int tt = 0; tt < 4; ++tt) {
            int r = ((ty << 2) + tt) << 1;
            float m0 = redM[r], m1 = redM[r + 1];
            int   i0 = redI[r], i1 = redI[r + 1];
            if (m1 > m0 || (m1 == m0 && i1 < i0)) { M[tt] = m1; MI[tt] = i1; }
            else                                  { M[tt] = m0; MI[tt] = i0; }
        }
        // 2) exp + denominator (overwrite acc2 with exp values)
        #pragma unroll
        for (int tt = 0; tt < 4; ++tt) {
            float s = 0.0f;
            #pragma unroll
            for (int h = 0; h < 8; ++h) {
                unsigned long long v = acc2[tt * 8 + h];
                float elo = __expf(lo32(v) - M[tt]);
                float ehi = __expf(hi32(v) - M[tt]);
                s += elo + ehi;
                acc2[tt * 8 + h] = pack2b(elo, ehi);
            }
            #pragma unroll
            for (int off = 16; off > 0; off >>= 1)
                s += __shfl_down_sync(0xffffffffu, s, off);
            if ((tx & 31) == 0) redZ[((((ty << 2) + tt) << 1)) + half] = s;
        }
        __syncthreads();
        float Zq[4];
        #pragma unroll
        for (int tt = 0; tt < 4; ++tt) {
            int r = ((ty << 2) + tt) << 1;
            Zq[tt] = 0.25f / (redZ[r] + redZ[r + 1]);   // softmax norm * 1/L
        }
        // 3) avg-probs accumulate via gmem RMW (L2-resident: same thread owns
        //    the same cells every layer -> no races, no smem, no final pass)
        #pragma unroll
        for (int tt = 0; tt < 4; ++tt) {
            int token = token0 + (ty << 2) + tt;
            unsigned long long iz = pack2(Zq[tt]);
            unsigned long long* Pg =
                (unsigned long long*)(out + OFF_AVG + (token << 10));
            #pragma unroll
            for (int j = 0; j < 4; ++j) {
                unsigned long long* pp = Pg + ((((j << 8) + (tx << 2))) >> 1);
                ulonglong2 pv;
                if (l == 0) { pv.x = 0ULL; pv.y = 0ULL; }
                else        { pv = *(ulonglong2*)pp; }
                ffma2(pv.x, acc2[tt * 8 + j * 2 + 0], iz);
                ffma2(pv.y, acc2[tt * 8 + j * 2 + 1], iz);
                *(ulonglong2*)pp = pv;
            }
            if (tx == 0) out[OFF_IDX + token * 4 + l] = (float)MI[tt];
            float4 q = *(const float4*)(cb + (((l << 10) + MI[tt]) << 8) + (tx << 2));
            int qi = token * 256 + (l << 6) + tx;          // float4 units
            ((float4*)out)[(OFF_Q     >> 2) + qi] = q;     // quantized
            ((float4*)out)[(OFF_QUANT >> 2) + qi] = q;     // quant (identical values)
        }
        // no trailing barrier needed: next layer's buffers/red arrays are
        // ordered by its own chunk-loop and epilogue barriers (disjoint addrs)
    }
}

extern "C" void kernel_launch(void* const* d_in, const int* in_sizes, int n_in,
                              void* d_out, int out_size)
{
    const float* x    = (const float*)d_in[0];
    const float* cb   = (const float*)d_in[1];
    const float* temp = (const float*)d_in[2];
    float* out = (float*)d_out;
    (void)in_sizes; (void)n_in; (void)out_size;

    // pre-pass: transpose codebook into cbT_g (d-major)
    transpose_cb<<<dim3(8, 32, 4), dim3(32, 8)>>>(cb);

    size_t smem = SM_FLOATS * sizeof(float);   // ~136.4 KB (< 227 KB sm_103a cap)
    cudaFuncSetAttribute(ahq_kernel, cudaFuncAttributeMaxDynamicSharedMemorySize, (int)smem);
    ahq_kernel<<<T_TOKENS / TM, NTHREADS, smem>>>(x, cb, temp, out);
}